// round 2
// baseline (speedup 1.0000x reference)
#include <cuda_runtime.h>
#include <cuda_bf16.h>

typedef unsigned long long u64;

#define BT  256   // threads per block
#define XPT 4     // vectors (x's) per thread
#define KW  256   // codewords
#define NP  128   // codeword pairs

__device__ __forceinline__ u64 pk2(float lo, float hi) {
    u64 r;
    asm("mov.b64 %0, {%1, %2};" : "=l"(r) : "f"(lo), "f"(hi));
    return r;
}
__device__ __forceinline__ void upk2(u64 v, float& lo, float& hi) {
    asm("mov.b64 {%0, %1}, %2;" : "=f"(lo), "=f"(hi) : "l"(v));
}
// Blackwell packed fp32 FMA: d.lo = a.lo*b.lo + c.lo ; d.hi = a.hi*b.hi + c.hi
__device__ __forceinline__ u64 ffma2(u64 a, u64 b, u64 c) {
    u64 d;
    asm("fma.rn.f32x2 %0, %1, %2, %3;" : "=l"(d) : "l"(a), "l"(b), "l"(c));
    return d;
}

__global__ void __launch_bounds__(BT)
vq_kernel(const float4* __restrict__ X,
          const float4* __restrict__ C,
          float4* __restrict__ outX,
          float* __restrict__ outS,
          int B)
{
    // Packed codebook: pair p covers codewords (2p, 2p+1)
    __shared__ ulonglong2 sAB[NP];   // (dim0 pair, dim1 pair)
    __shared__ ulonglong2 sCD[NP];   // (dim2 pair, dim3 pair)
    __shared__ u64        sQ[NP];    // (||c||^2 pair)
    __shared__ float4     sCW[KW];   // raw codewords for the final gather

    const int t = threadIdx.x;

    if (t < NP) {
        float4 a = C[2 * t];
        float4 b = C[2 * t + 1];
        sAB[t] = make_ulonglong2(pk2(a.x, b.x), pk2(a.y, b.y));
        sCD[t] = make_ulonglong2(pk2(a.z, b.z), pk2(a.w, b.w));
        float qa = a.x * a.x + a.y * a.y + a.z * a.z + a.w * a.w;
        float qb = b.x * b.x + b.y * b.y + b.z * b.z + b.w * b.w;
        sQ[t] = pk2(qa, qb);
    }
    sCW[t] = C[t];
    __syncthreads();

    const int base = blockIdx.x * (BT * XPT) + t;

    // Per-x state: y_i = -2*x_i broadcast-packed, running best (val, idx)
    u64 y0[XPT], y1[XPT], y2[XPT], y3[XPT];
    float bv[XPT];
    int   bi[XPT];

#pragma unroll
    for (int j = 0; j < XPT; j++) {
        int idx = base + j * BT;
        float4 x = (idx < B) ? X[idx] : make_float4(0.f, 0.f, 0.f, 0.f);
        float m0 = -2.0f * x.x, m1 = -2.0f * x.y, m2 = -2.0f * x.z, m3 = -2.0f * x.w;
        y0[j] = pk2(m0, m0);
        y1[j] = pk2(m1, m1);
        y2[j] = pk2(m2, m2);
        y3[j] = pk2(m3, m3);
        bv[j] = 3.402823466e38f;
        bi[j] = 0;
    }

    // val_k = ||c_k||^2 - 2 x . c_k   (same argmin as full distance)
#pragma unroll 8
    for (int p = 0; p < NP; p++) {
        const ulonglong2 ab = sAB[p];
        const ulonglong2 cd = sCD[p];
        const u64        q  = sQ[p];
#pragma unroll
        for (int j = 0; j < XPT; j++) {
            u64 acc = ffma2(y0[j], ab.x, q);
            acc = ffma2(y1[j], ab.y, acc);
            acc = ffma2(y2[j], cd.x, acc);
            acc = ffma2(y3[j], cd.y, acc);
            float lo, hi;
            upk2(acc, lo, hi);
            // strict <, ascending k: first-occurrence tie-break like jnp.argmin
            if (lo < bv[j]) { bv[j] = lo; bi[j] = 2 * p; }
            if (hi < bv[j]) { bv[j] = hi; bi[j] = 2 * p + 1; }
        }
    }

#pragma unroll
    for (int j = 0; j < XPT; j++) {
        int idx = base + j * BT;
        if (idx < B) {
            outX[idx] = sCW[bi[j]];
            outS[idx] = (float)bi[j];   // harness reads d_out as float32
        }
    }
}

extern "C" void kernel_launch(void* const* d_in, const int* in_sizes, int n_in,
                              void* d_out, int out_size)
{
    const float4* X = (const float4*)d_in[0];   // [B, 4] fp32
    const float4* C = (const float4*)d_in[1];   // [256, 4] fp32 codebook

    const int B = in_sizes[0] / 4;

    float4* outX = (float4*)d_out;                      // hatX [B,4] fp32
    float*  outS = (float*)d_out + 4 * (size_t)B;       // state [B] as fp32

    const int grid = (B + BT * XPT - 1) / (BT * XPT);
    vq_kernel<<<grid, BT>>>(X, C, outX, outS, B);
}

// round 3
// speedup vs baseline: 1.0071x; 1.0071x over previous
#include <cuda_runtime.h>
#include <cuda_bf16.h>

typedef unsigned long long u64;

#define BT  256   // threads per block
#define XPT 4     // vectors per thread
#define KW  256   // codewords
#define NP  128   // codeword pairs
#define GP  4     // pairs per group (8 codewords)
#define NG  (NP/GP)  // 32 groups

__device__ __forceinline__ u64 pk2(float lo, float hi) {
    u64 r;
    asm("mov.b64 %0, {%1, %2};" : "=l"(r) : "f"(lo), "f"(hi));
    return r;
}
__device__ __forceinline__ void upk2(u64 v, float& lo, float& hi) {
    asm("mov.b64 {%0, %1}, %2;" : "=f"(lo), "=f"(hi) : "l"(v));
}
// Blackwell packed fp32 FMA: d.lo = a.lo*b.lo + c.lo ; d.hi = a.hi*b.hi + c.hi
__device__ __forceinline__ u64 ffma2(u64 a, u64 b, u64 c) {
    u64 d;
    asm("fma.rn.f32x2 %0, %1, %2, %3;" : "=l"(d) : "l"(a), "l"(b), "l"(c));
    return d;
}
// packed min via two FMNMX on the halves (exact IEEE min: returns an input bitwise)
__device__ __forceinline__ u64 fmin2(u64 a, u64 b) {
    float al, ah, bl, bh;
    upk2(a, al, ah); upk2(b, bl, bh);
    return pk2(fminf(al, bl), fminf(ah, bh));
}

__global__ void __launch_bounds__(BT)
vq_kernel(const float4* __restrict__ X,
          const float4* __restrict__ C,
          float4* __restrict__ outX,
          float* __restrict__ outS,
          int B)
{
    // Packed codebook: pair p covers codewords (2p, 2p+1)
    __shared__ ulonglong2 sAB[NP];   // (dim0 pair, dim1 pair)
    __shared__ ulonglong2 sCD[NP];   // (dim2 pair, dim3 pair)
    __shared__ u64        sQ[NP];    // (||c||^2 pair)
    __shared__ float4     sCW[KW];   // raw codewords for final gather

    const int t = threadIdx.x;

    if (t < NP) {
        float4 a = C[2 * t];
        float4 b = C[2 * t + 1];
        sAB[t] = make_ulonglong2(pk2(a.x, b.x), pk2(a.y, b.y));
        sCD[t] = make_ulonglong2(pk2(a.z, b.z), pk2(a.w, b.w));
        float qa = a.x * a.x + a.y * a.y + a.z * a.z + a.w * a.w;
        float qb = b.x * b.x + b.y * b.y + b.z * b.z + b.w * b.w;
        sQ[t] = pk2(qa, qb);
    }
    sCW[t] = C[t];
    __syncthreads();

    const int base = blockIdx.x * (BT * XPT) + t;

    u64 y0[XPT], y1[XPT], y2[XPT], y3[XPT];
    float bv[XPT];
    int   gid[XPT];

#pragma unroll
    for (int j = 0; j < XPT; j++) {
        int idx = base + j * BT;
        float4 x = (idx < B) ? X[idx] : make_float4(0.f, 0.f, 0.f, 0.f);
        float m0 = -2.0f * x.x, m1 = -2.0f * x.y, m2 = -2.0f * x.z, m3 = -2.0f * x.w;
        y0[j] = pk2(m0, m0);
        y1[j] = pk2(m1, m1);
        y2[j] = pk2(m2, m2);
        y3[j] = pk2(m3, m3);
        bv[j] = 3.402823466e38f;
        gid[j] = 0;
    }

    // Main loop: val_k = ||c_k||^2 - 2 x.c_k  (same argmin as full distance).
    // Track only (min value, winning group of 8) — index bookkeeping amortized 8x.
#pragma unroll 8
    for (int g = 0; g < NG; g++) {
        u64 m[XPT];
#pragma unroll
        for (int i = 0; i < GP; i++) {
            const ulonglong2 ab = sAB[g * GP + i];   // broadcast LDS, conflict-free
            const ulonglong2 cd = sCD[g * GP + i];
            const u64        q  = sQ[g * GP + i];
#pragma unroll
            for (int j = 0; j < XPT; j++) {
                u64 acc = ffma2(y0[j], ab.x, q);
                acc = ffma2(y1[j], ab.y, acc);
                acc = ffma2(y2[j], cd.x, acc);
                acc = ffma2(y3[j], cd.y, acc);
                m[j] = (i == 0) ? acc : fmin2(m[j], acc);
            }
        }
#pragma unroll
        for (int j = 0; j < XPT; j++) {
            float lo, hi;
            upk2(m[j], lo, hi);
            float gm = fminf(lo, hi);
            if (gm < bv[j]) gid[j] = g;      // strict <: earlier group wins ties
            bv[j] = fminf(bv[j], gm);        // short FMNMX chain (lat 4)
        }
    }

    // Recovery: recompute the winning group's 8 distances with the bitwise-identical
    // FFMA2 chain; IEEE min returns inputs exactly, so equality match is guaranteed.
    // Scan pairs descending, hi before lo, so the smallest index wins (jnp.argmin).
#pragma unroll
    for (int j = 0; j < XPT; j++) {
        const int pb = gid[j] * GP;
        int bi = 0;
#pragma unroll
        for (int i = GP - 1; i >= 0; i--) {
            const ulonglong2 ab = sAB[pb + i];   // divergent LDS, once per vector
            const ulonglong2 cd = sCD[pb + i];
            const u64        q  = sQ[pb + i];
            u64 acc = ffma2(y0[j], ab.x, q);
            acc = ffma2(y1[j], ab.y, acc);
            acc = ffma2(y2[j], cd.x, acc);
            acc = ffma2(y3[j], cd.y, acc);
            float lo, hi;
            upk2(acc, lo, hi);
            const int k = 2 * (pb + i);
            if (hi == bv[j]) bi = k + 1;
            if (lo == bv[j]) bi = k;
        }
        const int idx = base + j * BT;
        if (idx < B) {
            outX[idx] = sCW[bi];
            outS[idx] = (float)bi;   // harness reads d_out as float32
        }
    }
}

extern "C" void kernel_launch(void* const* d_in, const int* in_sizes, int n_in,
                              void* d_out, int out_size)
{
    const float4* X = (const float4*)d_in[0];   // [B, 4] fp32
    const float4* C = (const float4*)d_in[1];   // [256, 4] fp32 codebook

    const int B = in_sizes[0] / 4;

    float4* outX = (float4*)d_out;                  // hatX [B,4] fp32
    float*  outS = (float*)d_out + 4 * (size_t)B;   // state [B] as fp32

    const int grid = (B + BT * XPT - 1) / (BT * XPT);
    vq_kernel<<<grid, BT>>>(X, C, outX, outS, B);
}

// round 4
// speedup vs baseline: 1.1314x; 1.1234x over previous
#include <cuda_runtime.h>
#include <cuda_bf16.h>

typedef unsigned long long u64;

#define BT  256   // threads per block
#define XPT 4     // vectors per thread
#define KW  256   // codewords
#define NP  128   // codeword pairs

__device__ __forceinline__ u64 pk2(float lo, float hi) {
    u64 r;
    asm("mov.b64 %0, {%1, %2};" : "=l"(r) : "f"(lo), "f"(hi));
    return r;
}
__device__ __forceinline__ void upk2(u64 v, float& lo, float& hi) {
    asm("mov.b64 {%0, %1}, %2;" : "=f"(lo), "=f"(hi) : "l"(v));
}
// Blackwell packed fp32 FMA: d.lo = a.lo*b.lo + c.lo ; d.hi = a.hi*b.hi + c.hi
__device__ __forceinline__ u64 ffma2(u64 a, u64 b, u64 c) {
    u64 d;
    asm("fma.rn.f32x2 %0, %1, %2, %3;" : "=l"(d) : "l"(a), "l"(b), "l"(c));
    return d;
}

__global__ void __launch_bounds__(BT, 4)
vq_kernel(const float4* __restrict__ X,
          const float4* __restrict__ C,
          float4* __restrict__ outX,
          float* __restrict__ outS,
          int B)
{
    // Packed codebook: pair p covers codewords (2p, 2p+1)
    __shared__ ulonglong2 sAB[NP];   // (dim0 pair, dim1 pair)
    __shared__ ulonglong2 sCD[NP];   // (dim2 pair, dim3 pair)
    __shared__ u64        sQ[NP];    // (||c||^2 pair)
    __shared__ float4     sCW[KW];   // raw codewords for final gather

    const int t = threadIdx.x;

    if (t < NP) {
        float4 a = C[2 * t];
        float4 b = C[2 * t + 1];
        sAB[t] = make_ulonglong2(pk2(a.x, b.x), pk2(a.y, b.y));
        sCD[t] = make_ulonglong2(pk2(a.z, b.z), pk2(a.w, b.w));
        float qa = a.x * a.x + a.y * a.y + a.z * a.z + a.w * a.w;
        float qb = b.x * b.x + b.y * b.y + b.z * b.z + b.w * b.w;
        sQ[t] = pk2(qa, qb);
    }
    sCW[t] = C[t];
    __syncthreads();

    const int base = blockIdx.x * (BT * XPT) + t;

    u64 y0[XPT], y1[XPT], y2[XPT], y3[XPT];
    float bv[XPT];
    int   pid[XPT];

#pragma unroll
    for (int j = 0; j < XPT; j++) {
        int idx = base + j * BT;
        float4 x = (idx < B) ? X[idx] : make_float4(0.f, 0.f, 0.f, 0.f);
        float m0 = -2.0f * x.x, m1 = -2.0f * x.y, m2 = -2.0f * x.z, m3 = -2.0f * x.w;
        y0[j] = pk2(m0, m0);
        y1[j] = pk2(m1, m1);
        y2[j] = pk2(m2, m2);
        y3[j] = pk2(m3, m3);
        bv[j] = 3.402823466e38f;
        pid[j] = 0;
    }

    // Main loop: val_k = ||c_k||^2 - 2 x.c_k  (same argmin as full distance).
    // Per pair: 4 packed FFMA2 + 4 short-latency alu (pair-min, cmp, pid sel, bv min).
#pragma unroll 8
    for (int p = 0; p < NP; p++) {
        const ulonglong2 ab = sAB[p];    // broadcast LDS, conflict-free
        const ulonglong2 cd = sCD[p];
        const u64        q  = sQ[p];
#pragma unroll
        for (int j = 0; j < XPT; j++) {
            u64 acc = ffma2(y0[j], ab.x, q);
            acc = ffma2(y1[j], ab.y, acc);
            acc = ffma2(y2[j], cd.x, acc);
            acc = ffma2(y3[j], cd.y, acc);
            float lo, hi;
            upk2(acc, lo, hi);
            float pv = fminf(lo, hi);
            if (pv < bv[j]) pid[j] = p;      // strict <: earlier pair wins ties
            bv[j] = fminf(bv[j], pv);        // FMNMX chain, lat 4
        }
    }

    // Recovery: replay the winning pair's bitwise-identical FFMA2 chain (3 divergent
    // LDS, addresses spread over 8 x 16B residues -> mild conflicts). FMNMX returns an
    // input exactly, so hi<lo resolves the within-pair index; ties prefer lo (= smaller
    // index), matching jnp.argmin first-occurrence.
#pragma unroll
    for (int j = 0; j < XPT; j++) {
        const int p = pid[j];
        const ulonglong2 ab = sAB[p];
        const ulonglong2 cd = sCD[p];
        const u64        q  = sQ[p];
        u64 acc = ffma2(y0[j], ab.x, q);
        acc = ffma2(y1[j], ab.y, acc);
        acc = ffma2(y2[j], cd.x, acc);
        acc = ffma2(y3[j], cd.y, acc);
        float lo, hi;
        upk2(acc, lo, hi);
        const int bi = 2 * p + ((hi < lo) ? 1 : 0);
        const int idx = base + j * BT;
        if (idx < B) {
            outX[idx] = sCW[bi];
            outS[idx] = (float)bi;   // harness reads d_out as float32
        }
    }
}

extern "C" void kernel_launch(void* const* d_in, const int* in_sizes, int n_in,
                              void* d_out, int out_size)
{
    const float4* X = (const float4*)d_in[0];   // [B, 4] fp32
    const float4* C = (const float4*)d_in[1];   // [256, 4] fp32 codebook

    const int B = in_sizes[0] / 4;

    float4* outX = (float4*)d_out;                  // hatX [B,4] fp32
    float*  outS = (float*)d_out + 4 * (size_t)B;   // state [B] as fp32

    const int grid = (B + BT * XPT - 1) / (BT * XPT);
    vq_kernel<<<grid, BT>>>(X, C, outX, outS, B);
}

// round 5
// speedup vs baseline: 1.1362x; 1.0043x over previous
#include <cuda_runtime.h>
#include <cuda_bf16.h>

typedef unsigned long long u64;

#define BT  256   // threads per block
#define XPT 2     // vectors per thread (lowered: buys registers -> occupancy)
#define KW  256   // codewords
#define NP  128   // codeword pairs

__device__ __forceinline__ u64 pk2(float lo, float hi) {
    u64 r;
    asm("mov.b64 %0, {%1, %2};" : "=l"(r) : "f"(lo), "f"(hi));
    return r;
}
__device__ __forceinline__ void upk2(u64 v, float& lo, float& hi) {
    asm("mov.b64 {%0, %1}, %2;" : "=f"(lo), "=f"(hi) : "l"(v));
}
// Blackwell packed fp32 FMA: d.lo = a.lo*b.lo + c.lo ; d.hi = a.hi*b.hi + c.hi
__device__ __forceinline__ u64 ffma2(u64 a, u64 b, u64 c) {
    u64 d;
    asm("fma.rn.f32x2 %0, %1, %2, %3;" : "=l"(d) : "l"(a), "l"(b), "l"(c));
    return d;
}

__global__ void __launch_bounds__(BT, 6)
vq_kernel(const float4* __restrict__ X,
          const float4* __restrict__ C,
          float4* __restrict__ outX,
          float* __restrict__ outS,
          int B)
{
    // Packed codebook: pair p covers codewords (2p, 2p+1)
    __shared__ ulonglong2 sAB[NP];   // (dim0 pair, dim1 pair)
    __shared__ ulonglong2 sCD[NP];   // (dim2 pair, dim3 pair)
    __shared__ u64        sQ[NP];    // (||c||^2 pair)
    __shared__ float4     sCW[KW];   // raw codewords for final gather

    const int t = threadIdx.x;

    if (t < NP) {
        float4 a = C[2 * t];
        float4 b = C[2 * t + 1];
        sAB[t] = make_ulonglong2(pk2(a.x, b.x), pk2(a.y, b.y));
        sCD[t] = make_ulonglong2(pk2(a.z, b.z), pk2(a.w, b.w));
        float qa = a.x * a.x + a.y * a.y + a.z * a.z + a.w * a.w;
        float qb = b.x * b.x + b.y * b.y + b.z * b.z + b.w * b.w;
        sQ[t] = pk2(qa, qb);
    }
    sCW[t] = C[t];
    __syncthreads();

    const int base = blockIdx.x * (BT * XPT) + t;

    u64 y0[XPT], y1[XPT], y2[XPT], y3[XPT];
    float bv[XPT];
    int   pid[XPT];

#pragma unroll
    for (int j = 0; j < XPT; j++) {
        int idx = base + j * BT;
        float4 x = (idx < B) ? X[idx] : make_float4(0.f, 0.f, 0.f, 0.f);
        float m0 = -2.0f * x.x, m1 = -2.0f * x.y, m2 = -2.0f * x.z, m3 = -2.0f * x.w;
        y0[j] = pk2(m0, m0);
        y1[j] = pk2(m1, m1);
        y2[j] = pk2(m2, m2);
        y3[j] = pk2(m3, m3);
        bv[j] = 3.402823466e38f;
        pid[j] = 0;
    }

    // Main loop: val_k = ||c_k||^2 - 2 x.c_k  (same argmin as full distance).
    // Per pair per vector: 4 packed FFMA2 (fma pipe) + 4 short-latency alu.
#pragma unroll 8
    for (int p = 0; p < NP; p++) {
        const ulonglong2 ab = sAB[p];    // broadcast LDS, conflict-free
        const ulonglong2 cd = sCD[p];
        const u64        q  = sQ[p];
#pragma unroll
        for (int j = 0; j < XPT; j++) {
            u64 acc = ffma2(y0[j], ab.x, q);
            acc = ffma2(y1[j], ab.y, acc);
            acc = ffma2(y2[j], cd.x, acc);
            acc = ffma2(y3[j], cd.y, acc);
            float lo, hi;
            upk2(acc, lo, hi);
            float pv = fminf(lo, hi);
            if (pv < bv[j]) pid[j] = p;      // strict <: earlier pair wins ties
            bv[j] = fminf(bv[j], pv);        // FMNMX chain, lat 4
        }
    }

    // Recovery: replay the winning pair's bitwise-identical FFMA2 chain (3 divergent
    // LDS per vector, once). FMNMX returns an input exactly, so hi<lo resolves the
    // within-pair index; ties prefer lo (= smaller index) matching jnp.argmin.
#pragma unroll
    for (int j = 0; j < XPT; j++) {
        const int p = pid[j];
        const ulonglong2 ab = sAB[p];
        const ulonglong2 cd = sCD[p];
        const u64        q  = sQ[p];
        u64 acc = ffma2(y0[j], ab.x, q);
        acc = ffma2(y1[j], ab.y, acc);
        acc = ffma2(y2[j], cd.x, acc);
        acc = ffma2(y3[j], cd.y, acc);
        float lo, hi;
        upk2(acc, lo, hi);
        const int bi = 2 * p + ((hi < lo) ? 1 : 0);
        const int idx = base + j * BT;
        if (idx < B) {
            outX[idx] = sCW[bi];
            outS[idx] = (float)bi;   // harness reads d_out as float32
        }
    }
}

extern "C" void kernel_launch(void* const* d_in, const int* in_sizes, int n_in,
                              void* d_out, int out_size)
{
    const float4* X = (const float4*)d_in[0];   // [B, 4] fp32
    const float4* C = (const float4*)d_in[1];   // [256, 4] fp32 codebook

    const int B = in_sizes[0] / 4;

    float4* outX = (float4*)d_out;                  // hatX [B,4] fp32
    float*  outS = (float*)d_out + 4 * (size_t)B;   // state [B] as fp32

    const int grid = (B + BT * XPT - 1) / (BT * XPT);
    vq_kernel<<<grid, BT>>>(X, C, outX, outS, B);
}

// round 6
// speedup vs baseline: 1.1368x; 1.0005x over previous
#include <cuda_runtime.h>
#include <cuda_bf16.h>

typedef unsigned long long u64;

#define BT  256   // threads per block
#define XPT 3     // vectors per thread (saddle point: LDS amortization vs registers)
#define KW  256   // codewords
#define NP  128   // codeword pairs

__device__ __forceinline__ u64 pk2(float lo, float hi) {
    u64 r;
    asm("mov.b64 %0, {%1, %2};" : "=l"(r) : "f"(lo), "f"(hi));
    return r;
}
__device__ __forceinline__ void upk2(u64 v, float& lo, float& hi) {
    asm("mov.b64 {%0, %1}, %2;" : "=f"(lo), "=f"(hi) : "l"(v));
}
// Blackwell packed fp32 FMA: d.lo = a.lo*b.lo + c.lo ; d.hi = a.hi*b.hi + c.hi
__device__ __forceinline__ u64 ffma2(u64 a, u64 b, u64 c) {
    u64 d;
    asm("fma.rn.f32x2 %0, %1, %2, %3;" : "=l"(d) : "l"(a), "l"(b), "l"(c));
    return d;
}

__global__ void __launch_bounds__(BT, 5)
vq_kernel(const float4* __restrict__ X,
          const float4* __restrict__ C,
          float4* __restrict__ outX,
          float* __restrict__ outS,
          int B)
{
    // Packed codebook: pair p covers codewords (2p, 2p+1)
    __shared__ ulonglong2 sAB[NP];      // (dim0 pair, dim1 pair)
    __shared__ ulonglong2 sCD[NP];      // (dim2 pair, dim3 pair)
    __shared__ ulonglong2 sQ2[NP / 2];  // ||c||^2 for pairs (2i, 2i+1) in one 16B slot
    __shared__ float4     sCW[KW];      // raw codewords for final gather

    const int t = threadIdx.x;

    if (t < NP) {
        float4 a = C[2 * t];
        float4 b = C[2 * t + 1];
        sAB[t] = make_ulonglong2(pk2(a.x, b.x), pk2(a.y, b.y));
        sCD[t] = make_ulonglong2(pk2(a.z, b.z), pk2(a.w, b.w));
        float qa = a.x * a.x + a.y * a.y + a.z * a.z + a.w * a.w;
        float qb = b.x * b.x + b.y * b.y + b.z * b.z + b.w * b.w;
        // q of pair t goes to slot t>>1, half t&1
        u64 qp = pk2(qa, qb);
        if (t & 1) sQ2[t >> 1].y = qp; else sQ2[t >> 1].x = qp;
    }
    sCW[t] = C[t];
    __syncthreads();

    const int base = blockIdx.x * (BT * XPT) + t;

    u64 y0[XPT], y1[XPT], y2[XPT], y3[XPT];
    float bv[XPT];
    int   pid[XPT];

#pragma unroll
    for (int j = 0; j < XPT; j++) {
        int idx = base + j * BT;
        float4 x = (idx < B) ? X[idx] : make_float4(0.f, 0.f, 0.f, 0.f);
        float m0 = -2.0f * x.x, m1 = -2.0f * x.y, m2 = -2.0f * x.z, m3 = -2.0f * x.w;
        y0[j] = pk2(m0, m0);
        y1[j] = pk2(m1, m1);
        y2[j] = pk2(m2, m2);
        y3[j] = pk2(m3, m3);
        bv[j] = 3.402823466e38f;
        pid[j] = 0;
    }

    // Main loop over pair-duos: val_k = ||c_k||^2 - 2 x.c_k (same argmin as full dist).
    // LDS per 2 pairs: 4x LDS.128 (ab/cd) + 1x LDS.128 (both q's) = 2.5 loads/pair.
#pragma unroll 4
    for (int p2 = 0; p2 < NP / 2; p2++) {
        const ulonglong2 qq = sQ2[p2];   // broadcast LDS, conflict-free
        {
            const int p = 2 * p2;
            const ulonglong2 ab = sAB[p];
            const ulonglong2 cd = sCD[p];
#pragma unroll
            for (int j = 0; j < XPT; j++) {
                u64 acc = ffma2(y0[j], ab.x, qq.x);
                acc = ffma2(y1[j], ab.y, acc);
                acc = ffma2(y2[j], cd.x, acc);
                acc = ffma2(y3[j], cd.y, acc);
                float lo, hi;
                upk2(acc, lo, hi);
                float pv = fminf(lo, hi);
                if (pv < bv[j]) pid[j] = p;      // strict <: earlier pair wins ties
                bv[j] = fminf(bv[j], pv);
            }
        }
        {
            const int p = 2 * p2 + 1;
            const ulonglong2 ab = sAB[p];
            const ulonglong2 cd = sCD[p];
#pragma unroll
            for (int j = 0; j < XPT; j++) {
                u64 acc = ffma2(y0[j], ab.x, qq.y);
                acc = ffma2(y1[j], ab.y, acc);
                acc = ffma2(y2[j], cd.x, acc);
                acc = ffma2(y3[j], cd.y, acc);
                float lo, hi;
                upk2(acc, lo, hi);
                float pv = fminf(lo, hi);
                if (pv < bv[j]) pid[j] = p;
                bv[j] = fminf(bv[j], pv);
            }
        }
    }

    // Recovery: replay the winning pair's bitwise-identical FFMA2 chain (3 divergent
    // LDS per vector, once). FMNMX returns an input exactly, so hi<lo resolves the
    // within-pair index; ties prefer lo (= smaller index) matching jnp.argmin.
#pragma unroll
    for (int j = 0; j < XPT; j++) {
        const int p = pid[j];
        const ulonglong2 ab = sAB[p];
        const ulonglong2 cd = sCD[p];
        const ulonglong2 qq = sQ2[p >> 1];
        const u64 q = (p & 1) ? qq.y : qq.x;
        u64 acc = ffma2(y0[j], ab.x, q);
        acc = ffma2(y1[j], ab.y, acc);
        acc = ffma2(y2[j], cd.x, acc);
        acc = ffma2(y3[j], cd.y, acc);
        float lo, hi;
        upk2(acc, lo, hi);
        const int bi = 2 * p + ((hi < lo) ? 1 : 0);
        const int idx = base + j * BT;
        if (idx < B) {
            outX[idx] = sCW[bi];
            outS[idx] = (float)bi;   // harness reads d_out as float32
        }
    }
}

extern "C" void kernel_launch(void* const* d_in, const int* in_sizes, int n_in,
                              void* d_out, int out_size)
{
    const float4* X = (const float4*)d_in[0];   // [B, 4] fp32
    const float4* C = (const float4*)d_in[1];   // [256, 4] fp32 codebook

    const int B = in_sizes[0] / 4;

    float4* outX = (float4*)d_out;                  // hatX [B,4] fp32
    float*  outS = (float*)d_out + 4 * (size_t)B;   // state [B] as fp32

    const int grid = (B + BT * XPT - 1) / (BT * XPT);
    vq_kernel<<<grid, BT>>>(X, C, outX, outS, B);
}